// round 8
// baseline (speedup 1.0000x reference)
#include <cuda_runtime.h>
#include <cuda_fp16.h>
#include <cstdint>

// LatticeCNN on GB300 — closed-form lattice conv decomposition, fp16 mma.sync,
// fp16-resident activations/weights, cp.async double-buffered staging.
//
// join conv  == pointwise with 2-D prefix-summed weights
// meet conv  == pointwise(suffix weights) + x-prefix row strips + y-prefix col
//               strips + 2-D-prefix corner term

#define ALPHA  0.5f
#define SLOPE  0.01f
#define S      32
#define FOUT   128

__device__ __forceinline__ uint32_t pack_f16x2(float lo, float hi) {
    uint32_t r;
    asm("cvt.rn.f16x2.f32 %0, %1, %2;" : "=r"(r) : "f"(hi), "f"(lo));
    return r;
}
__device__ __forceinline__ uint32_t smem_u32(const void* p) {
    uint32_t a;
    asm("{ .reg .u64 t; cvta.to.shared.u64 t, %1; cvt.u32.u64 %0, t; }"
        : "=r"(a) : "l"(p));
    return a;
}
#define CP16(dst, src) \
    asm volatile("cp.async.cg.shared.global [%0], [%1], 16;" \
                 :: "r"(dst), "l"(src) : "memory")
#define CP_COMMIT() asm volatile("cp.async.commit_group;" ::: "memory")
#define CP_WAIT(n)  asm volatile("cp.async.wait_group %0;" :: "n"(n) : "memory")

__device__ __forceinline__ void mma16(float (&d)[4], const uint4& a,
                                      uint32_t b0, uint32_t b1) {
    asm volatile(
        "mma.sync.aligned.m16n8k16.row.col.f32.f16.f16.f32 "
        "{%0,%1,%2,%3}, {%4,%5,%6,%7}, {%8,%9}, {%0,%1,%2,%3};"
        : "+f"(d[0]), "+f"(d[1]), "+f"(d[2]), "+f"(d[3])
        : "r"(a.x), "r"(a.y), "r"(a.z), "r"(a.w), "r"(b0), "r"(b1));
}

// ---------------- device scratch (no allocation allowed) ----------------
__device__ __half d_Xt0h[1024 * 64 * 64];    // layer0 input, pixel-major fp16
__device__ __half d_Yth [1024 * 64 * 128];   // layer0 out / layer1 in, fp16
__device__ float  d_Yt2 [1024 * 64 * 128];   // layer1 out (pixel-major, fp32)
__device__ __half d_WCT [225 * 128 * FOUT];  // pointwise weights [class][g][f]
__device__ __half d_MRST[64 * 128 * FOUT];   // row-suffix  [a*8+q][g][f]
__device__ __half d_MCST[64 * 128 * FOUT];   // col-suffix  [p*8+b][g][f]
__device__ __half d_MWT [64 * 128 * FOUT];   // raw meet    [a*8+b][g][f]
__device__ float  d_G   [224 * 64 * FOUT];   // row strip tiles  G[a][y]
__device__ float  d_CG  [224 * 64 * FOUT];   // col strip tiles  CG[b][x]
__device__ float  d_H   [49  * 64 * FOUT];   // corner tiles     H[a][b]

// ---------------- transposes ----------------
__global__ void transpose_h_k(__half* __restrict__ dst, const float* __restrict__ src,
                              int R, int C)   // dst[C][R] fp16 = src[R][C] fp32
{
    __shared__ float tile[32][33];
    int c0 = blockIdx.x * 32, r0 = blockIdx.y * 32;
    #pragma unroll
    for (int i = 0; i < 4; i++)
        tile[threadIdx.y + 8 * i][threadIdx.x] =
            src[(size_t)(r0 + threadIdx.y + 8 * i) * C + c0 + threadIdx.x];
    __syncthreads();
    #pragma unroll
    for (int i = 0; i < 4; i++)
        dst[(size_t)(c0 + threadIdx.y + 8 * i) * R + r0 + threadIdx.x] =
            __float2half_rn(tile[threadIdx.x][threadIdx.y + 8 * i]);
}

__global__ void transpose_k(float* __restrict__ dst, const float* __restrict__ src,
                            int R, int C)
{
    __shared__ float tile[32][33];
    int c0 = blockIdx.x * 32, r0 = blockIdx.y * 32;
    #pragma unroll
    for (int i = 0; i < 4; i++)
        tile[threadIdx.y + 8 * i][threadIdx.x] =
            src[(size_t)(r0 + threadIdx.y + 8 * i) * C + c0 + threadIdx.x];
    __syncthreads();
    #pragma unroll
    for (int i = 0; i < 4; i++)
        dst[(size_t)(c0 + threadIdx.y + 8 * i) * R + r0 + threadIdx.x] =
            tile[threadIdx.x][threadIdx.y + 8 * i];
}

// ---------------- per-layer weight-table prep (fp16 [g][f] tables) ------
__global__ void prep_k(const float* __restrict__ mw, const float* __restrict__ jw,
                       __half* __restrict__ WCT, __half* __restrict__ MRST,
                       __half* __restrict__ MCST, __half* __restrict__ MWT, int Fin)
{
    int idx = blockIdx.x * blockDim.x + threadIdx.x;
    if (idx >= Fin * FOUT) return;
    int f = idx >> 7, g = idx & 127;
    int ss = Fin * FOUT;
    int src = f * FOUT + g;          // original [a][b][f][g]
    int tb  = g * Fin + f;           // transposed [g][f]

    float m[8][8];
    #pragma unroll
    for (int a = 0; a < 8; a++)
        #pragma unroll
        for (int b = 0; b < 8; b++) {
            m[a][b] = mw[(a * 8 + b) * ss + src];
            MWT[(a * 8 + b) * ss + tb] = __float2half_rn(m[a][b]);
        }

    {   // MCS[p][b] = sum_{a>=p} mw[a][b]
        float col[8];
        #pragma unroll
        for (int b = 0; b < 8; b++) col[b] = 0.f;
        #pragma unroll
        for (int p = 7; p >= 0; p--)
            #pragma unroll
            for (int b = 0; b < 8; b++) {
                col[b] += m[p][b];
                MCST[(p * 8 + b) * ss + tb] = __float2half_rn(col[b]);
            }
    }
    #pragma unroll
    for (int a = 0; a < 8; a++) {    // MRS[a][q] = sum_{b>=q}
        #pragma unroll
        for (int q = 6; q >= 0; q--) m[a][q] += m[a][q + 1];
        #pragma unroll
        for (int q = 0; q < 8; q++) MRST[(a * 8 + q) * ss + tb] = __float2half_rn(m[a][q]);
    }
    #pragma unroll
    for (int b = 0; b < 8; b++)      // -> 2-D suffix MS
        #pragma unroll
        for (int a = 6; a >= 0; a--) m[a][b] += m[a + 1][b];

    float j[8][8];
    #pragma unroll
    for (int a = 0; a < 8; a++)
        #pragma unroll
        for (int b = 0; b < 8; b++)
            j[a][b] = jw[(a * 8 + b) * ss + src];
    #pragma unroll
    for (int a = 0; a < 8; a++)
        #pragma unroll
        for (int b = 1; b < 8; b++) j[a][b] += j[a][b - 1];
    #pragma unroll
    for (int b = 0; b < 8; b++)
        #pragma unroll
        for (int a = 1; a < 8; a++) j[a][b] += j[a - 1][b];

    for (int cx = 0; cx < 15; cx++) {
        int ax = cx < 8 ? 0 : cx - 7;
        int jx = cx < 8 ? cx : 7;
        for (int cy = 0; cy < 15; cy++) {
            int ay = cy < 8 ? 0 : cy - 7;
            int jy = cy < 8 ? cy : 7;
            WCT[(cx * 15 + cy) * ss + tb] =
                __float2half_rn((1.0f - ALPHA) * m[ax][ay] + ALPHA * j[jx][jy]);
        }
    }
}

// ---------------- async staging of one unit (X 64 rows + W 128 rows) -------
template <int FIN>
__device__ __forceinline__ void stage_async(uint32_t sbuf,
                                            const __half* __restrict__ X,
                                            const __half* __restrict__ W)
{
    constexpr int CR  = FIN / 8;          // 16B chunks per row
    constexpr int LDB = FIN * 2 + 16;     // smem row bytes
    const int tid = threadIdx.x;
    uint32_t sw = sbuf + 64 * LDB;
    #pragma unroll
    for (int c = tid; c < 64 * CR; c += 256) {
        int r = c / CR, k = c % CR;
        CP16(sbuf + r * LDB + k * 16, X + r * FIN + k * 8);
    }
    #pragma unroll
    for (int c = tid; c < 128 * CR; c += 256) {
        int r = c / CR, k = c % CR;
        CP16(sw + r * LDB + k * 16, W + r * FIN + k * 8);
    }
}

// ---------------- MMA compute from staged smem ----------------
template <int FIN>
__device__ __forceinline__ void unit_compute(const __half* __restrict__ Xs,
                                             float (&acc)[2][4][4])
{
    constexpr int LDh = FIN + 8;
    const __half* Ws = Xs + 64 * LDh;
    const int lane = threadIdx.x & 31, wid = threadIdx.x >> 5;
    const int wm = wid >> 2, wn = wid & 3;
    const __half* Ax = Xs + (wm * 32 + (lane >> 2)) * LDh + (lane & 3) * 2;
    const __half* Bx = Ws + (wn * 32 + (lane >> 2)) * LDh + (lane & 3) * 2;

    #pragma unroll
    for (int kt = 0; kt < FIN / 16; kt++) {
        const int k0 = kt * 16;
        uint4 a0, a1;
        a0.x = *(const uint32_t*)(Ax + k0);
        a0.y = *(const uint32_t*)(Ax + 8 * LDh + k0);
        a0.z = *(const uint32_t*)(Ax + k0 + 8);
        a0.w = *(const uint32_t*)(Ax + 8 * LDh + k0 + 8);
        a1.x = *(const uint32_t*)(Ax + 16 * LDh + k0);
        a1.y = *(const uint32_t*)(Ax + 24 * LDh + k0);
        a1.z = *(const uint32_t*)(Ax + 16 * LDh + k0 + 8);
        a1.w = *(const uint32_t*)(Ax + 24 * LDh + k0 + 8);
        uint32_t b[4][2];
        #pragma unroll
        for (int nt = 0; nt < 4; nt++) {
            b[nt][0] = *(const uint32_t*)(Bx + nt * 8 * LDh + k0);
            b[nt][1] = *(const uint32_t*)(Bx + nt * 8 * LDh + k0 + 8);
        }
        #pragma unroll
        for (int nt = 0; nt < 4; nt++) {
            mma16(acc[0][nt], a0, b[nt][0], b[nt][1]);
            mma16(acc[1][nt], a1, b[nt][0], b[nt][1]);
        }
    }
}

// ---------------- strips/corner: 497 units, 2 per block, double-buffered ---
template <int FIN>
__device__ __forceinline__ void resolve_strip(int u, const __half* Xt,
    const __half* MRST, const __half* MCST, const __half* MWT,
    float* G, float* CG, float* H,
    const __half** X, const __half** W, float** dst)
{
    size_t ss = (size_t)FIN * FOUT;
    if (u < 224) {
        int a = u >> 5, Y = u & 31;
        int q = Y > 24 ? Y - 24 : 0;
        *X = Xt + (size_t)((a + 24) * S + Y) * 64 * FIN;
        *W = MRST + (size_t)(a * 8 + q) * ss;
        *dst = G + (size_t)u * 64 * FOUT;
    } else if (u < 448) {
        int t = u - 224;
        int b = t >> 5, Xc = t & 31;
        int p = Xc > 24 ? Xc - 24 : 0;
        *X = Xt + (size_t)(Xc * S + b + 24) * 64 * FIN;
        *W = MCST + (size_t)(p * 8 + b) * ss;
        *dst = CG + (size_t)t * 64 * FOUT;
    } else {
        int t = u - 448;
        int a = t / 7, b = t % 7;
        *X = Xt + (size_t)((a + 24) * S + b + 24) * 64 * FIN;
        *W = MWT + (size_t)(a * 8 + b) * ss;
        *dst = H + (size_t)t * 64 * FOUT;
    }
}

__device__ __forceinline__ void store_strip(float* __restrict__ dst,
                                            float (&acc)[2][4][4])
{
    int lane = threadIdx.x & 31, wid = threadIdx.x >> 5;
    int wm = wid >> 2, wn = wid & 3;
    int r0 = wm * 32 + (lane >> 2);
    #pragma unroll
    for (int mt = 0; mt < 2; mt++)
        #pragma unroll
        for (int nt = 0; nt < 4; nt++) {
            int g = wn * 32 + nt * 8 + (lane & 3) * 2;
            int r = r0 + mt * 16;
            *(float2*)(dst + r * FOUT + g)       = make_float2(acc[mt][nt][0], acc[mt][nt][1]);
            *(float2*)(dst + (r + 8) * FOUT + g) = make_float2(acc[mt][nt][2], acc[mt][nt][3]);
        }
}

template <int FIN>
__global__ void __launch_bounds__(256, 2) strips_mc(
    const __half* __restrict__ Xt, const __half* __restrict__ MRST,
    const __half* __restrict__ MCST, const __half* __restrict__ MWT,
    float* __restrict__ G, float* __restrict__ CG, float* __restrict__ H)
{
    extern __shared__ __half smh[];
    constexpr int LDh = FIN + 8;
    constexpr int BUF = 192 * LDh;          // halfwords per buffer
    uint32_t sbase = smem_u32(smh);
    int u0 = blockIdx.x * 2;
    int u1 = (u0 + 1 < 497) ? u0 + 1 : u0;

    const __half *X0, *W0, *X1, *W1; float *d0, *d1;
    resolve_strip<FIN>(u0, Xt, MRST, MCST, MWT, G, CG, H, &X0, &W0, &d0);
    resolve_strip<FIN>(u1, Xt, MRST, MCST, MWT, G, CG, H, &X1, &W1, &d1);

    stage_async<FIN>(sbase, X0, W0);               CP_COMMIT();
    stage_async<FIN>(sbase + BUF * 2, X1, W1);     CP_COMMIT();

    CP_WAIT(1); __syncthreads();
    {
        float acc[2][4][4] = {};
        unit_compute<FIN>(smh, acc);
        store_strip(d0, acc);
    }
    CP_WAIT(0); __syncthreads();
    {
        float acc[2][4][4] = {};
        unit_compute<FIN>(smh + BUF, acc);
        store_strip(d1, acc);
    }
}

// ---------------- merged prefix pass: rows(G) + rows(CG) + 2-D(H) ----------
__global__ void prefix_all_k(float* __restrict__ G, float* __restrict__ CG,
                             float* __restrict__ H)
{
    int bid = blockIdx.x;
    if (bid < 2048) {
        int t = bid * 256 + threadIdx.x;
        float* buf = (t < 32 * 8192) ? G : CG;
        int tt = t & (32 * 8192 - 1);
        int yy = tt >> 13, mg = tt & 8191;
        float run = 0.f;
        #pragma unroll
        for (int a = 0; a < 7; a++) {
            int idx = (a * 32 + yy) * 8192 + mg;
            run += buf[idx];
            buf[idx] = run;
        }
    } else {
        int mg = (bid - 2048) * 256 + threadIdx.x;
        float colA[7];
        #pragma unroll
        for (int b = 0; b < 7; b++) colA[b] = 0.f;
        #pragma unroll
        for (int a = 0; a < 7; a++) {
            float run = 0.f;
            #pragma unroll
            for (int b = 0; b < 7; b++) {
                int idx = (a * 7 + b) * 8192 + mg;
                run += H[idx];
                colA[b] += run;
                H[idx] = colA[b];
            }
        }
    }
}

// ---------------- combine: 1024 pixels, 2 per block, double-buffered -------
template <int FIN, bool OUT_HALF>
__device__ __forceinline__ void combine_epi(int p, float (&acc)[2][4][4],
    const float* __restrict__ Gc, const float* __restrict__ CGc,
    const float* __restrict__ Hc, const float* __restrict__ mb,
    const float* __restrict__ jb, void* __restrict__ Yout)
{
    int X = p >> 5, Y = p & 31;
    const float ms = 1.0f - ALPHA;
    const float* Gp = (X >= 25) ? Gc + (size_t)((X - 25) * S + Y) * 64 * FOUT : 0;
    const float* Cp = (Y >= 25) ? CGc + (size_t)((Y - 25) * S + X) * 64 * FOUT : 0;
    const float* Hp = (X >= 25 && Y >= 25)
        ? Hc + (size_t)((X - 25) * 7 + (Y - 25)) * 64 * FOUT : 0;

    int lane = threadIdx.x & 31, wid = threadIdx.x >> 5;
    int wm = wid >> 2, wn = wid & 3;
    int r0 = wm * 32 + (lane >> 2);

    #pragma unroll
    for (int nt = 0; nt < 4; nt++) {
        int g = wn * 32 + nt * 8 + (lane & 3) * 2;
        float2 bias = make_float2(ms * mb[g]     + ALPHA * jb[g],
                                  ms * mb[g + 1] + ALPHA * jb[g + 1]);
        #pragma unroll
        for (int mt = 0; mt < 2; mt++) {
            #pragma unroll
            for (int half = 0; half < 2; half++) {
                int r = r0 + mt * 16 + half * 8;
                float v0 = acc[mt][nt][half * 2], v1 = acc[mt][nt][half * 2 + 1];
                if (Gp) {
                    float2 s2 = *(const float2*)(Gp + r * FOUT + g);
                    v0 += ms * s2.x; v1 += ms * s2.y;
                }
                if (Cp) {
                    float2 s2 = *(const float2*)(Cp + r * FOUT + g);
                    v0 += ms * s2.x; v1 += ms * s2.y;
                }
                if (Hp) {
                    float2 s2 = *(const float2*)(Hp + r * FOUT + g);
                    v0 += ms * s2.x; v1 += ms * s2.y;
                }
                v0 += bias.x; v1 += bias.y;
                v0 = fmaxf(v0, SLOPE * v0);
                v1 = fmaxf(v1, SLOPE * v1);
                if (OUT_HALF) {
                    __half* O = (__half*)Yout + (size_t)p * 64 * FOUT;
                    *(uint32_t*)(O + r * FOUT + g) = pack_f16x2(v0, v1);
                } else {
                    float* O = (float*)Yout + (size_t)p * 64 * FOUT;
                    *(float2*)(O + r * FOUT + g) = make_float2(v0, v1);
                }
            }
        }
    }
}

template <int FIN, bool OUT_HALF>
__global__ void __launch_bounds__(256, 2) combine_mc(
    const __half* __restrict__ Xt, const __half* __restrict__ WCT,
    const float* __restrict__ Gc, const float* __restrict__ CGc,
    const float* __restrict__ Hc, const float* __restrict__ mb,
    const float* __restrict__ jb, void* __restrict__ Yout)
{
    extern __shared__ __half smh[];
    constexpr int LDh = FIN + 8;
    constexpr int BUF = 192 * LDh;
    uint32_t sbase = smem_u32(smh);
    size_t ss = (size_t)FIN * FOUT;

    int p0 = blockIdx.x * 2, p1 = p0 + 1;
    int X0 = p0 >> 5, Y0 = p0 & 31, X1 = p1 >> 5, Y1 = p1 & 31;
    int c0 = (X0 <= 24 ? (X0 < 7 ? X0 : 7) : X0 - 17) * 15
           + (Y0 <= 24 ? (Y0 < 7 ? Y0 : 7) : Y0 - 17);
    int c1 = (X1 <= 24 ? (X1 < 7 ? X1 : 7) : X1 - 17) * 15
           + (Y1 <= 24 ? (Y1 < 7 ? Y1 : 7) : Y1 - 17);

    stage_async<FIN>(sbase, Xt + (size_t)p0 * 64 * FIN, WCT + (size_t)c0 * ss);
    CP_COMMIT();
    stage_async<FIN>(sbase + BUF * 2, Xt + (size_t)p1 * 64 * FIN, WCT + (size_t)c1 * ss);
    CP_COMMIT();

    CP_WAIT(1); __syncthreads();
    {
        float acc[2][4][4] = {};
        unit_compute<FIN>(smh, acc);
        combine_epi<FIN, OUT_HALF>(p0, acc, Gc, CGc, Hc, mb, jb, Yout);
    }
    CP_WAIT(0); __syncthreads();
    {
        float acc[2][4][4] = {};
        unit_compute<FIN>(smh + BUF, acc);
        combine_epi<FIN, OUT_HALF>(p1, acc, Gc, CGc, Hc, mb, jb, Yout);
    }
}

// ---------------- host launch ----------------
extern "C" void kernel_launch(void* const* d_in, const int* in_sizes, int n_in,
                              void* d_out, int out_size)
{
    const float* x   = (const float*)d_in[0];
    const float* mw0 = (const float*)d_in[5];
    const float* mb0 = (const float*)d_in[6];
    const float* jw0 = (const float*)d_in[7];
    const float* jb0 = (const float*)d_in[8];
    const float* mw1 = (const float*)d_in[9];
    const float* mb1 = (const float*)d_in[10];
    const float* jw1 = (const float*)d_in[11];
    const float* jb1 = (const float*)d_in[12];
    float* out = (float*)d_out;

    __half *Xt0h, *Yth, *WCT, *MRST, *MCST, *MWT;
    float *Yt2, *G, *CG, *H;
    cudaGetSymbolAddress((void**)&Xt0h, d_Xt0h);
    cudaGetSymbolAddress((void**)&Yth,  d_Yth);
    cudaGetSymbolAddress((void**)&Yt2,  d_Yt2);
    cudaGetSymbolAddress((void**)&WCT,  d_WCT);
    cudaGetSymbolAddress((void**)&MRST, d_MRST);
    cudaGetSymbolAddress((void**)&MCST, d_MCST);
    cudaGetSymbolAddress((void**)&MWT,  d_MWT);
    cudaGetSymbolAddress((void**)&G,    d_G);
    cudaGetSymbolAddress((void**)&CG,   d_CG);
    cudaGetSymbolAddress((void**)&H,    d_H);

    const int smem64  = 2 * 192 * (64 + 8)  * 2;   //  55296 B
    const int smem128 = 2 * 192 * (128 + 8) * 2;   // 104448 B
    cudaFuncSetAttribute(strips_mc<64>,          cudaFuncAttributeMaxDynamicSharedMemorySize, smem64);
    cudaFuncSetAttribute((const void*)combine_mc<64, true>,
                         cudaFuncAttributeMaxDynamicSharedMemorySize, smem64);
    cudaFuncSetAttribute(strips_mc<128>,         cudaFuncAttributeMaxDynamicSharedMemorySize, smem128);
    cudaFuncSetAttribute((const void*)combine_mc<128, false>,
                         cudaFuncAttributeMaxDynamicSharedMemorySize, smem128);

    dim3 tb(32, 8);
    // x [4096][1024] fp32 -> Xt0h [1024][4096] fp16
    transpose_h_k<<<dim3(1024 / 32, 4096 / 32), tb>>>(Xt0h, x, 4096, 1024);

    // ---- layer 0: Fin = 64 ----
    prep_k<<<(64 * 128) / 256, 256>>>(mw0, jw0, WCT, MRST, MCST, MWT, 64);
    strips_mc<64><<<249, 256, smem64>>>(Xt0h, MRST, MCST, MWT, G, CG, H);
    prefix_all_k<<<2080, 256>>>(G, CG, H);
    combine_mc<64, true><<<512, 256, smem64>>>(Xt0h, WCT, G, CG, H, mb0, jb0, Yth);

    // ---- layer 1: Fin = 128 ----
    prep_k<<<(128 * 128) / 256, 256>>>(mw1, jw1, WCT, MRST, MCST, MWT, 128);
    strips_mc<128><<<249, 256, smem128>>>(Yth, MRST, MCST, MWT, G, CG, H);
    prefix_all_k<<<2080, 256>>>(G, CG, H);
    combine_mc<128, false><<<512, 256, smem128>>>(Yth, WCT, G, CG, H, mb1, jb1, Yt2);

    // Yt2 [1024][8192] -> out [8192][1024]
    transpose_k<<<dim3(8192 / 32, 1024 / 32), tb>>>(out, Yt2, 1024, 8192);
}